// round 6
// baseline (speedup 1.0000x reference)
#include <cuda_runtime.h>

// Depthwise Conv1d: B=32, C=128, L=8192, kernel=3, stride=1, pad=1, fp32.
// out[b,c,l] = w[c,0]*x[b,c,l-1] + w[c,1]*x[b,c,l] + w[c,2]*x[b,c,l+1] + bias[c]
//
// R6: grid-strided ILP raised to 8. All vector loads front-batched (8
// outstanding LDG.128 per thread) to maximize in-flight DRAM bytes; halos
// front-batched after them (L1/L2 hits). Grid stride = 512 rows (multiple
// of CHANS) so the per-channel taps are loaded once per thread.

#define BATCH 32
#define CHANS 128
#define LEN   8192
#define LEN4  (LEN / 4)          // 2048 float4 per row
#define ROWS  (BATCH * CHANS)    // 4096
#define NTHREADS 256
#define ITER 8
#define TOTAL4   (ROWS * LEN4)               // 8,388,608 float4
#define NTHREADS_TOTAL (TOTAL4 / ITER)       // 1,048,576
#define NBLOCKS  (NTHREADS_TOTAL / NTHREADS) // 4096

// rows between iterations: NTHREADS_TOTAL / LEN4 = 512 (multiple of CHANS)

__global__ __launch_bounds__(NTHREADS)
void dwconv1d_kernel(const float* __restrict__ x,
                     const float* __restrict__ w,
                     const float* __restrict__ bias,
                     float* __restrict__ out)
{
    const unsigned int gid    = blockIdx.x * NTHREADS + threadIdx.x;
    const unsigned int stride = NTHREADS_TOTAL; // uniform grid stride (float4 units)

    // ---- front-batched vector loads (8 outstanding LDG.128, coalesced) ----
    float4 v[ITER];
#pragma unroll
    for (int i = 0; i < ITER; i++)
        v[i] = reinterpret_cast<const float4*>(x)[gid + i * stride];

    // ---- taps: channel identical across iterations (stride = 512 rows) ----
    const unsigned int c = (gid >> 11) & (CHANS - 1);
    const float w0 = __ldg(&w[c * 3 + 0]);
    const float w1 = __ldg(&w[c * 3 + 1]);
    const float w2 = __ldg(&w[c * 3 + 2]);
    const float bb = __ldg(&bias[c]);

    // ---- front-batched halo loads (mostly L1/L2 hits) ----
    float left[ITER], right[ITER];
#pragma unroll
    for (int i = 0; i < ITER; i++) {
        unsigned int idx = gid + i * stride;
        unsigned int j   = idx & (LEN4 - 1);
        const float* xe  = x + 4u * (size_t)idx; // element pointer to v[i].x
        left[i]  = (j == 0)        ? 0.0f : __ldg(xe - 1);
        right[i] = (j == LEN4 - 1) ? 0.0f : __ldg(xe + 4);
    }

    // ---- compute + store ----
#pragma unroll
    for (int i = 0; i < ITER; i++) {
        float4 o;
        o.x = fmaf(w0, left[i], fmaf(w1, v[i].x, fmaf(w2, v[i].y, bb)));
        o.y = fmaf(w0, v[i].x,  fmaf(w1, v[i].y, fmaf(w2, v[i].z, bb)));
        o.z = fmaf(w0, v[i].y,  fmaf(w1, v[i].z, fmaf(w2, v[i].w, bb)));
        o.w = fmaf(w0, v[i].z,  fmaf(w1, v[i].w, fmaf(w2, right[i], bb)));
        reinterpret_cast<float4*>(out)[gid + i * stride] = o;
    }
}

extern "C" void kernel_launch(void* const* d_in, const int* in_sizes, int n_in,
                              void* d_out, int out_size)
{
    const float* x    = (const float*)d_in[0];
    const float* w    = (const float*)d_in[1];
    const float* bias = (const float*)d_in[2];
    float* out        = (float*)d_out;

    dwconv1d_kernel<<<NBLOCKS, NTHREADS>>>(x, w, bias, out);
}

// round 7
// speedup vs baseline: 1.0391x; 1.0391x over previous
#include <cuda_runtime.h>

// Depthwise Conv1d: B=32, C=128, L=8192, kernel=3, stride=1, pad=1, fp32.
// out[b,c,l] = w[c,0]*x[b,c,l-1] + w[c,1]*x[b,c,l] + w[c,2]*x[b,c,l+1] + bias[c]
//
// R7 = R4 (grid-strided ILP=4, per-instruction coalesced) + R3 (shuffle
// halos). The 8 scalar halo LDGs per thread (R4's dominant L1-wavefront
// cost) are replaced by 8 SHFLs; only lanes 0/31 load halo scalars.
// Grid stride = 1024 rows exactly, so: j (within-row position) and c
// (channel) are identical across all 4 iterations -> single edge branch,
// single tap load.

#define BATCH 32
#define CHANS 128
#define LEN   8192
#define LEN4  (LEN / 4)          // 2048 float4 per row
#define ROWS  (BATCH * CHANS)    // 4096
#define NTHREADS 256
#define ITER 4
#define TOTAL4   (ROWS * LEN4)               // 8,388,608 float4
#define NTHREADS_TOTAL (TOTAL4 / ITER)       // 2,097,152
#define NBLOCKS  (NTHREADS_TOTAL / NTHREADS) // 8192

__global__ __launch_bounds__(NTHREADS)
void dwconv1d_kernel(const float* __restrict__ x,
                     const float* __restrict__ w,
                     const float* __restrict__ bias,
                     float* __restrict__ out)
{
    const unsigned int gid    = blockIdx.x * NTHREADS + threadIdx.x;
    const unsigned int stride = NTHREADS_TOTAL;   // float4 units; = 1024 rows
    const unsigned int lane   = threadIdx.x & 31;
    const unsigned int j      = gid & (LEN4 - 1); // same for all iterations

    // ---- front-batched vector loads (4 outstanding LDG.128, coalesced) ----
    float4 v[ITER];
#pragma unroll
    for (int i = 0; i < ITER; i++)
        v[i] = reinterpret_cast<const float4*>(x)[gid + i * stride];

    // ---- per-channel taps (identical across iterations) ----
    const unsigned int c = (gid >> 11) & (CHANS - 1);
    const float w0 = __ldg(&w[c * 3 + 0]);
    const float w1 = __ldg(&w[c * 3 + 1]);
    const float w2 = __ldg(&w[c * 3 + 2]);
    const float bb = __ldg(&bias[c]);

    // ---- halos via warp shuffle; edge lanes via scalar loads ----
    float left[ITER], right[ITER];
#pragma unroll
    for (int i = 0; i < ITER; i++) {
        left[i]  = __shfl_up_sync(0xffffffffu, v[i].w, 1);
        right[i] = __shfl_down_sync(0xffffffffu, v[i].x, 1);
    }
    if (lane == 0) {
#pragma unroll
        for (int i = 0; i < ITER; i++)
            left[i] = (j == 0) ? 0.0f
                               : __ldg(x + 4u * (size_t)(gid + i * stride) - 1);
    }
    if (lane == 31) {
#pragma unroll
        for (int i = 0; i < ITER; i++)
            right[i] = (j == LEN4 - 1) ? 0.0f
                                       : __ldg(x + 4u * (size_t)(gid + i * stride) + 4);
    }

    // ---- compute + store ----
#pragma unroll
    for (int i = 0; i < ITER; i++) {
        float4 o;
        o.x = fmaf(w0, left[i], fmaf(w1, v[i].x, fmaf(w2, v[i].y, bb)));
        o.y = fmaf(w0, v[i].x,  fmaf(w1, v[i].y, fmaf(w2, v[i].z, bb)));
        o.z = fmaf(w0, v[i].y,  fmaf(w1, v[i].z, fmaf(w2, v[i].w, bb)));
        o.w = fmaf(w0, v[i].z,  fmaf(w1, v[i].w, fmaf(w2, right[i], bb)));
        reinterpret_cast<float4*>(out)[gid + i * stride] = o;
    }
}

extern "C" void kernel_launch(void* const* d_in, const int* in_sizes, int n_in,
                              void* d_out, int out_size)
{
    const float* x    = (const float*)d_in[0];
    const float* w    = (const float*)d_in[1];
    const float* bias = (const float*)d_in[2];
    float* out        = (float*)d_out;

    dwconv1d_kernel<<<NBLOCKS, NTHREADS>>>(x, w, bias, out);
}